// round 14
// baseline (speedup 1.0000x reference)
#include <cuda_runtime.h>
#include <math.h>
#include <stdint.h>

#define NTOK 16384   // B*T
#define DDIM 1024
#define NEXP 8
#define HDIM 512

#define BM 128
#define BN 128
#define BK 32

#define ASTRIDE 36                       // floats; conflict-free A frag reads
#define A_BYTES (BM * ASTRIDE * 4)       // 18432
#define B_BYTES (BK * BN * 4)            // 16384 (prepped/swizzled layout)
#define STAGE_BYTES (A_BYTES + B_BYTES)  // 34816
#define NSTAGE 4
#define SMEM_BYTES (NSTAGE * STAGE_BYTES)  // 139264; 1 CTA of 512 thr/SM

#define GT_THREADS 512                   // GEMM threads: 16 warps, warp tile 32x32

#define RT_THREADS 512
#define RT_SMEM (2 * DDIM * NEXP * 4)    // 65536: Wr + Wn cached per block (transposed)

// ---------------- device scratch ----------------
__device__ int   g_counts[NEXP];
__device__ int   g_tok [NEXP * NTOK];
__device__ float g_gate[NEXP * NTOK];
__device__ float g_xr  [(size_t)NTOK * DDIM];            // tf32-rounded x (router)
__device__ float g_Wdr [(size_t)NEXP * DDIM * HDIM];     // prepped Wd (swizzled tiles)
__device__ float g_Wur [(size_t)NEXP * HDIM * DDIM];     // prepped Wu (swizzled tiles)
__device__ float g_hidden[(size_t)NEXP * NTOK * HDIM];   // tf32-rounded gelu output

// ---------------- helpers ----------------
__device__ __forceinline__ float tf32r(float f) {
    uint32_t u;
    asm("cvt.rna.tf32.f32 %0, %1;" : "=r"(u) : "f"(f));
    return __uint_as_float(u);
}
__device__ __forceinline__ void mma_tf32(float c[4],
                                         uint32_t a0, uint32_t a1, uint32_t a2, uint32_t a3,
                                         uint32_t b0, uint32_t b1) {
    asm volatile(
        "mma.sync.aligned.m16n8k8.row.col.f32.tf32.tf32.f32 "
        "{%0,%1,%2,%3}, {%4,%5,%6,%7}, {%8,%9}, {%0,%1,%2,%3};"
        : "+f"(c[0]), "+f"(c[1]), "+f"(c[2]), "+f"(c[3])
        : "r"(a0), "r"(a1), "r"(a2), "r"(a3), "r"(b0), "r"(b1));
}
__device__ __forceinline__ void cp16(uint32_t dst, const void* src) {
    asm volatile("cp.async.cg.shared.global [%0], [%1], 16;" :: "r"(dst), "l"(src));
}
#define CP_COMMIT() asm volatile("cp.async.commit_group;" ::: "memory")
#define CP_WAIT(n)  asm volatile("cp.async.wait_group %0;" :: "n"(n) : "memory")

// ============================================================
// init: zero the output only (counters zeroed in prep_wd)
// ============================================================
__global__ void init_kernel(float* __restrict__ out) {
    size_t i = (size_t)blockIdx.x * blockDim.x + threadIdx.x;
    if (i < (size_t)NTOK * DDIM / 4)
        ((float4*)out)[i] = make_float4(0.f, 0.f, 0.f, 0.f);
}

// ============================================================
// prep: weights -> tf32-rounded, n-permuted + bank-swizzled tile layout
// (verified bit-exact since Round 6). Also zeroes the router counters.
// ============================================================
__global__ void prep_wd_kernel(const float* __restrict__ W) {
    int id = blockIdx.x * blockDim.x + threadIdx.x;   // 2^20 chunks
    if (blockIdx.x == 0 && threadIdx.x < NEXP) g_counts[threadIdx.x] = 0;
    int cp = id & 31;
    int k  = (id >> 5) & 1023;
    int nb = (id >> 15) & 3;
    int e  = id >> 17;
    int t  = k & 3;
    int hb = ((cp >> 3) & 3) ^ t;
    int wn = hb >> 1, v = hb & 1;
    int g  = (cp & 7) ^ ((t << 1) & 7);
    const float* src = W + (size_t)e * DDIM * HDIM + (size_t)k * HDIM + nb * 128 + wn * 64 + v * 32 + g;
    float4 o;
    o.x = tf32r(src[0]);
    o.y = tf32r(src[8]);
    o.z = tf32r(src[16]);
    o.w = tf32r(src[24]);
    ((float4*)g_Wdr)[id] = o;
}
__global__ void prep_wu_kernel(const float* __restrict__ W) {
    int id = blockIdx.x * blockDim.x + threadIdx.x;   // 2^20 chunks
    int cp = id & 31;
    int k  = (id >> 5) & 511;
    int nb = (id >> 14) & 7;
    int e  = id >> 17;
    int t  = k & 3;
    int hb = ((cp >> 3) & 3) ^ t;
    int wn = hb >> 1, v = hb & 1;
    int g  = (cp & 7) ^ ((t << 1) & 7);
    const float* src = W + (size_t)e * HDIM * DDIM + (size_t)k * DDIM + nb * 128 + wn * 64 + v * 32 + g;
    float4 o;
    o.x = tf32r(src[0]);
    o.y = tf32r(src[8]);
    o.z = tf32r(src[16]);
    o.w = tf32r(src[24]);
    ((float4*)g_Wur)[id] = o;
}

// ============================================================
// router — one warp per token; Wr/Wn cached TRANSPOSED in smem
// (conflict-free scalar LDS). FMA values/order identical -> same routing.
// ============================================================
__global__ __launch_bounds__(RT_THREADS) void router_kernel(
    const float* __restrict__ x,
    const float* __restrict__ Wr, const float* __restrict__ br,
    const float* __restrict__ Wn, const float* __restrict__ bn,
    const float* __restrict__ noise) {
    extern __shared__ __align__(16) float sWt[];   // [e][1024] Wr, then [e][1024] Wn
    int tid = threadIdx.x;
#pragma unroll
    for (int i = 0; i < 2; i++) {
        int d = tid + i * RT_THREADS;
        float4 r0 = ((const float4*)(Wr + (size_t)d * NEXP))[0];
        float4 r1 = ((const float4*)(Wr + (size_t)d * NEXP))[1];
        sWt[0 * 1024 + d] = r0.x; sWt[1 * 1024 + d] = r0.y;
        sWt[2 * 1024 + d] = r0.z; sWt[3 * 1024 + d] = r0.w;
        sWt[4 * 1024 + d] = r1.x; sWt[5 * 1024 + d] = r1.y;
        sWt[6 * 1024 + d] = r1.z; sWt[7 * 1024 + d] = r1.w;
        float4 n0 = ((const float4*)(Wn + (size_t)d * NEXP))[0];
        float4 n1 = ((const float4*)(Wn + (size_t)d * NEXP))[1];
        sWt[8192 + 0 * 1024 + d] = n0.x; sWt[8192 + 1 * 1024 + d] = n0.y;
        sWt[8192 + 2 * 1024 + d] = n0.z; sWt[8192 + 3 * 1024 + d] = n0.w;
        sWt[8192 + 4 * 1024 + d] = n1.x; sWt[8192 + 5 * 1024 + d] = n1.y;
        sWt[8192 + 6 * 1024 + d] = n1.z; sWt[8192 + 7 * 1024 + d] = n1.w;
    }
    __syncthreads();

    int gwarp = blockIdx.x * (RT_THREADS / 32) + (tid >> 5);
    int lane  = tid & 31;
    const float* xr = x + (size_t)gwarp * DDIM;
    float* xw = g_xr + (size_t)gwarp * DDIM;

    float accL[NEXP], accN[NEXP];
#pragma unroll
    for (int e = 0; e < NEXP; e++) { accL[e] = 0.f; accN[e] = 0.f; }

    for (int d = lane; d < DDIM; d += 32) {
        float xv = xr[d];
        xw[d] = tf32r(xv);
        accL[0] = fmaf(xv, sWt[0 * 1024 + d], accL[0]);
        accL[1] = fmaf(xv, sWt[1 * 1024 + d], accL[1]);
        accL[2] = fmaf(xv, sWt[2 * 1024 + d], accL[2]);
        accL[3] = fmaf(xv, sWt[3 * 1024 + d], accL[3]);
        accL[4] = fmaf(xv, sWt[4 * 1024 + d], accL[4]);
        accL[5] = fmaf(xv, sWt[5 * 1024 + d], accL[5]);
        accL[6] = fmaf(xv, sWt[6 * 1024 + d], accL[6]);
        accL[7] = fmaf(xv, sWt[7 * 1024 + d], accL[7]);
        accN[0] = fmaf(xv, sWt[8192 + 0 * 1024 + d], accN[0]);
        accN[1] = fmaf(xv, sWt[8192 + 1 * 1024 + d], accN[1]);
        accN[2] = fmaf(xv, sWt[8192 + 2 * 1024 + d], accN[2]);
        accN[3] = fmaf(xv, sWt[8192 + 3 * 1024 + d], accN[3]);
        accN[4] = fmaf(xv, sWt[8192 + 4 * 1024 + d], accN[4]);
        accN[5] = fmaf(xv, sWt[8192 + 5 * 1024 + d], accN[5]);
        accN[6] = fmaf(xv, sWt[8192 + 6 * 1024 + d], accN[6]);
        accN[7] = fmaf(xv, sWt[8192 + 7 * 1024 + d], accN[7]);
    }
#pragma unroll
    for (int off = 16; off > 0; off >>= 1) {
#pragma unroll
        for (int e = 0; e < NEXP; e++) {
            accL[e] += __shfl_down_sync(0xffffffffu, accL[e], off);
            accN[e] += __shfl_down_sync(0xffffffffu, accN[e], off);
        }
    }
    if (lane == 0) {
        float noisy[NEXP];
#pragma unroll
        for (int e = 0; e < NEXP; e++) {
            float nl = accN[e] + bn[e];
            float sp = fmaxf(nl, 0.f) + log1pf(expf(-fabsf(nl)));
            noisy[e] = accL[e] + br[e] + noise[(size_t)gwarp * NEXP + e] * sp;
        }
        int i1 = 0; float v1 = noisy[0];
#pragma unroll
        for (int e = 1; e < NEXP; e++) if (noisy[e] > v1) { v1 = noisy[e]; i1 = e; }
        int i2 = -1; float v2 = -3.4e38f;
#pragma unroll
        for (int e = 0; e < NEXP; e++) if (e != i1 && noisy[e] > v2) { v2 = noisy[e]; i2 = e; }

        float e2 = expf(v2 - v1);
        float s  = 1.0f + e2;
        float g1 = 1.0f / s;
        float g2 = e2 / s;

        int p1 = atomicAdd(&g_counts[i1], 1);
        g_tok [i1 * NTOK + p1] = gwarp;
        g_gate[i1 * NTOK + p1] = g1;
        int p2 = atomicAdd(&g_counts[i2], 1);
        g_tok [i2 * NTOK + p2] = gwarp;
        g_gate[i2 * NTOK + p2] = g2;
    }
}

// ============================================================
// GEMM machinery — CTA 128x128, 512 threads / 16 warps, warp tile 32x32
// (warp grid 4m x 4n), NSTAGE=4 cp.async, prefetch distance 2,
// single sync per iteration. Soundness:
//   iter i: load(i+2) -> CP_WAIT(2) -> sync -> compute(i)
//   RAW: wait(2) leaves groups i+1,i+2 pending => group(i) complete;
//        sync publishes all threads' stage-i bytes.
//   WAR: load(i+2) writes stage (i+2)%4 == (i-2)%4, last read by
//        compute(i-2), which precedes sync(i-1) for all threads,
//        and sync(i-1) precedes iter-i loads.
// ============================================================
struct Src {
    const float* arow[2];   // gathered A row ptrs (rows tid>>3, tid>>3 + 64)
    const float* bbase;     // prepped weight tile base (swizzled rows of 128 floats)
};

__device__ __forceinline__ void compute_stage(const char* smem, int st,
                                              int warp_m, int wq, int g, int t,
                                              float acc[2][4][4]) {
    const uint32_t* As = (const uint32_t*)(smem + st * STAGE_BYTES);
    const uint4*    Bs = (const uint4*)(smem + st * STAGE_BYTES + A_BYTES);
    const int glo  = g ^ ((t << 1) & 7);
    const int cidx = ((wq ^ t) << 3) | glo;
#pragma unroll
    for (int ks = 0; ks < 4; ks++) {
        int kk = ks * 8;
        uint32_t af[2][4];
#pragma unroll
        for (int mi = 0; mi < 2; mi++) {
            int mr = warp_m + mi * 16 + g;
            af[mi][0] = As[(mr    ) * ASTRIDE + kk + t];
            af[mi][1] = As[(mr + 8) * ASTRIDE + kk + t];
            af[mi][2] = As[(mr    ) * ASTRIDE + kk + t + 4];
            af[mi][3] = As[(mr + 8) * ASTRIDE + kk + t + 4];
        }
        uint4 b0 = Bs[(kk + t    ) * 32 + cidx];
        uint4 b1 = Bs[(kk + t + 4) * 32 + cidx];
#pragma unroll
        for (int mi = 0; mi < 2; mi++) {
            mma_tf32(acc[mi][0], af[mi][0], af[mi][1], af[mi][2], af[mi][3], b0.x, b1.x);
            mma_tf32(acc[mi][1], af[mi][0], af[mi][1], af[mi][2], af[mi][3], b0.y, b1.y);
            mma_tf32(acc[mi][2], af[mi][0], af[mi][1], af[mi][2], af[mi][3], b0.z, b1.z);
            mma_tf32(acc[mi][3], af[mi][0], af[mi][1], af[mi][2], af[mi][3], b0.w, b1.w);
        }
    }
}

#define LOAD_ST(s)                                                               \
    do {                                                                         \
        cp16(stA[s] + aoff0, gA0);                                               \
        cp16(stA[s] + aoff1, gA1);                                               \
        cp16(stB[s] + boff0, gB + (boff0 >> 2));                                 \
        cp16(stB[s] + boff1, gB + (boff1 >> 2));                                 \
        CP_COMMIT();                                                             \
        gA0 += BK; gA1 += BK; gB += BK * BN;                                     \
    } while (0)

#define GEMM_MAINLOOP(NITER)                                                     \
    uint32_t stA[NSTAGE], stB[NSTAGE];                                           \
    uint32_t aoff0, aoff1, boff0, boff1;                                         \
    const float* gA0;                                                            \
    const float* gA1;                                                            \
    const float* gB;                                                             \
    {                                                                            \
        uint32_t sbase = (uint32_t)__cvta_generic_to_shared(smem);               \
        _Pragma("unroll") for (int s = 0; s < NSTAGE; s++) {                     \
            stA[s] = sbase + s * STAGE_BYTES;                                    \
            stB[s] = stA[s] + A_BYTES;                                           \
        }                                                                        \
        int c16 = tid & 7;                                                       \
        aoff0 = (tid >> 3) * (ASTRIDE * 4) + c16 * 16;                           \
        aoff1 = ((tid >> 3) + 64) * (ASTRIDE * 4) + c16 * 16;                    \
        boff0 = (uint32_t)tid * 16;                                              \
        boff1 = (uint32_t)(tid + GT_THREADS) * 16;                               \
        gA0 = src.arow[0];                                                       \
        gA1 = src.arow[1];                                                       \
        gB  = src.bbase;                                                         \
    }                                                                            \
    LOAD_ST(0);                                                                  \
    LOAD_ST(1);                                                                  \
    {                                                                            \
        int st = 0;                                                              \
        for (int i = 0; i < (NITER); i++) {                                      \
            if (i + 2 < (NITER)) {                                               \
                LOAD_ST((st + 2) & 3);                                           \
                CP_WAIT(2);                                                      \
            } else if (i + 1 < (NITER)) { CP_WAIT(1); } else { CP_WAIT(0); }     \
            __syncthreads();                                                     \
            compute_stage(smem, st, warp_m, wq, g, t, acc);                      \
            st = (st + 1) & 3;                                                   \
        }                                                                        \
    }

// ============================================================
// grouped GEMM #1 — hidden = tf32r(gelu(x[toks] @ Wd + bd))
// ============================================================
__global__ __launch_bounds__(GT_THREADS, 1) void expert_down_mma(const float* __restrict__ bd)
{
    extern __shared__ __align__(16) char smem[];
    int e  = blockIdx.z;
    int ne = g_counts[e];
    int m0 = blockIdx.y * BM;
    if (m0 >= ne) return;
    int n0 = blockIdx.x * BN;

    int tid  = threadIdx.x;
    int lane = tid & 31;
    int wid  = tid >> 5;
    int warp_m = (wid & 3) * 32;
    int wq     = wid >> 2;          // 0..3 (32-col n chunk)
    int warp_n = wq * 32;
    int g = lane >> 2, t = lane & 3;

    Src src;
    int c16 = tid & 7;
#pragma unroll
    for (int j = 0; j < 2; j++) {
        int m = m0 + (tid >> 3) + 64 * j;
        int tok = (m < ne) ? g_tok[e * NTOK + m] : g_tok[e * NTOK + m0];
        src.arow[j] = g_xr + (size_t)tok * DDIM + c16 * 4;
    }
    src.bbase = g_Wdr + ((size_t)(e * 4 + blockIdx.x) * DDIM) * BN;

    float acc[2][4][4];
#pragma unroll
    for (int mi = 0; mi < 2; mi++)
#pragma unroll
        for (int ni = 0; ni < 4; ni++)
#pragma unroll
            for (int j = 0; j < 4; j++) acc[mi][ni][j] = 0.f;

    GEMM_MAINLOOP(DDIM / BK)

    // epilogue: bias + exact GELU + tf32 round
#pragma unroll
    for (int mi = 0; mi < 2; mi++) {
        int m1 = m0 + warp_m + mi * 16 + g;
        int m2 = m1 + 8;
#pragma unroll
        for (int ni = 0; ni < 4; ni++) {
            int n = n0 + warp_n + ni * 8 + 2 * t;
            float b0v = bd[e * HDIM + n];
            float b1v = bd[e * HDIM + n + 1];
            if (m1 < ne) {
                float h0 = acc[mi][ni][0] + b0v;
                float h1 = acc[mi][ni][1] + b1v;
                h0 = tf32r(0.5f * h0 * (1.0f + erff(h0 * 0.70710678118654752f)));
                h1 = tf32r(0.5f * h1 * (1.0f + erff(h1 * 0.70710678118654752f)));
                *(float2*)(g_hidden + ((size_t)e * NTOK + m1) * HDIM + n) = make_float2(h0, h1);
            }
            if (m2 < ne) {
                float h2 = acc[mi][ni][2] + b0v;
                float h3 = acc[mi][ni][3] + b1v;
                h2 = tf32r(0.5f * h2 * (1.0f + erff(h2 * 0.70710678118654752f)));
                h3 = tf32r(0.5f * h3 * (1.0f + erff(h3 * 0.70710678118654752f)));
                *(float2*)(g_hidden + ((size_t)e * NTOK + m2) * HDIM + n) = make_float2(h2, h3);
            }
        }
    }
}

// ============================================================
// grouped GEMM #2 — out[tok] += gate * (hidden @ Wu + bu)
// ============================================================
__global__ __launch_bounds__(GT_THREADS, 1) void expert_up_mma(
    const float* __restrict__ bu, float* __restrict__ out)
{
    extern __shared__ __align__(16) char smem[];
    int e  = blockIdx.z;
    int ne = g_counts[e];
    int m0 = blockIdx.y * BM;
    if (m0 >= ne) return;
    int n0 = blockIdx.x * BN;

    int tid  = threadIdx.x;
    int lane = tid & 31;
    int wid  = tid >> 5;
    int warp_m = (wid & 3) * 32;
    int wq     = wid >> 2;
    int warp_n = wq * 32;
    int g = lane >> 2, t = lane & 3;

    Src src;
    int c16 = tid & 7;
#pragma unroll
    for (int j = 0; j < 2; j++) {
        int m = m0 + (tid >> 3) + 64 * j;
        int mm = (m < ne) ? m : m0;   // clamp: garbage rows never reach valid accumulators
        src.arow[j] = g_hidden + ((size_t)e * NTOK + mm) * HDIM + c16 * 4;
    }
    src.bbase = g_Wur + ((size_t)(e * 8 + blockIdx.x) * HDIM) * BN;

    float acc[2][4][4];
#pragma unroll
    for (int mi = 0; mi < 2; mi++)
#pragma unroll
        for (int ni = 0; ni < 4; ni++)
#pragma unroll
            for (int j = 0; j < 4; j++) acc[mi][ni][j] = 0.f;

    GEMM_MAINLOOP(HDIM / BK)

    // epilogue: bias + gate * atomicAdd (2 commutative adds/element -> deterministic)
#pragma unroll
    for (int mi = 0; mi < 2; mi++) {
        int m1 = m0 + warp_m + mi * 16 + g;
        int m2 = m1 + 8;
        int   tok1 = 0, tok2 = 0;
        float gt1 = 0.f, gt2 = 0.f;
        if (m1 < ne) { tok1 = g_tok[e * NTOK + m1]; gt1 = g_gate[e * NTOK + m1]; }
        if (m2 < ne) { tok2 = g_tok[e * NTOK + m2]; gt2 = g_gate[e * NTOK + m2]; }
#pragma unroll
        for (int ni = 0; ni < 4; ni++) {
            int n = n0 + warp_n + ni * 8 + 2 * t;
            float b0v = bu[e * DDIM + n];
            float b1v = bu[e * DDIM + n + 1];
            if (m1 < ne) {
                atomicAdd(out + (size_t)tok1 * DDIM + n,     (acc[mi][ni][0] + b0v) * gt1);
                atomicAdd(out + (size_t)tok1 * DDIM + n + 1, (acc[mi][ni][1] + b1v) * gt1);
            }
            if (m2 < ne) {
                atomicAdd(out + (size_t)tok2 * DDIM + n,     (acc[mi][ni][2] + b0v) * gt2);
                atomicAdd(out + (size_t)tok2 * DDIM + n + 1, (acc[mi][ni][3] + b1v) * gt2);
            }
        }
    }
}

// ============================================================
// Host launcher — expert_down_mma kept at launch index 3 for ncu.
// Dependencies: prep_wd (zeroes counters) -> router ; router -> down ;
// init(out) -> up.
// ============================================================
extern "C" void kernel_launch(void* const* d_in, const int* in_sizes, int n_in,
                              void* d_out, int out_size) {
    const float* x     = (const float*)d_in[0];
    const float* Wr    = (const float*)d_in[1];
    const float* br    = (const float*)d_in[2];
    const float* Wn    = (const float*)d_in[3];
    const float* bn    = (const float*)d_in[4];
    const float* Wd    = (const float*)d_in[5];
    const float* bd    = (const float*)d_in[6];
    const float* Wu    = (const float*)d_in[7];
    const float* bu    = (const float*)d_in[8];
    const float* noise = (const float*)d_in[9];
    float* out = (float*)d_out;

    cudaFuncSetAttribute(expert_down_mma, cudaFuncAttributeMaxDynamicSharedMemorySize, SMEM_BYTES);
    cudaFuncSetAttribute(expert_up_mma,   cudaFuncAttributeMaxDynamicSharedMemorySize, SMEM_BYTES);
    cudaFuncSetAttribute(router_kernel,   cudaFuncAttributeMaxDynamicSharedMemorySize, RT_SMEM);

    prep_wd_kernel<<<(NEXP * DDIM * HDIM / 4) / 256, 256>>>(Wd);                       // idx 0
    prep_wu_kernel<<<(NEXP * HDIM * DDIM / 4) / 256, 256>>>(Wu);                       // idx 1
    router_kernel<<<NTOK / (RT_THREADS / 32), RT_THREADS, RT_SMEM>>>(x, Wr, br, Wn, bn, noise); // idx 2
    expert_down_mma<<<dim3(HDIM / BN, NTOK / BM, NEXP), GT_THREADS, SMEM_BYTES>>>(bd); // idx 3 (ncu)
    init_kernel<<<(NTOK * DDIM / 4 + 255) / 256, 256>>>(out);                          // idx 4
    expert_up_mma<<<dim3(DDIM / BN, NTOK / BM, NEXP), GT_THREADS, SMEM_BYTES>>>(bu, out); // idx 5
}

// round 15
// speedup vs baseline: 1.2081x; 1.2081x over previous
#include <cuda_runtime.h>
#include <math.h>
#include <stdint.h>

#define NTOK 16384   // B*T
#define DDIM 1024
#define NEXP 8
#define HDIM 512

#define BM 128
#define BN 128
#define BK 32

#define ASTRIDE 36                       // floats; conflict-free A frag reads
#define A_BYTES (BM * ASTRIDE * 4)       // 18432
#define B_BYTES (BK * BN * 4)            // 16384 (prepped/swizzled layout)
#define STAGE_BYTES (A_BYTES + B_BYTES)  // 34816
#define NSTAGE 3
#define SMEM_BYTES (NSTAGE * STAGE_BYTES)  // 104448; x2 CTAs = 208.9KB

#define RT_THREADS 512
#define RT_SMEM (2 * DDIM * NEXP * 4)    // 65536: Wr + Wn cached per block (transposed)

// prologue block ranges
#define PRO_WD_BLOCKS 4096               // 2^20 chunks / 256
#define PRO_WU_BLOCKS 4096
#define PRO_INIT_BLOCKS 16384            // NTOK*DDIM/4 / 256
#define PRO_BLOCKS (PRO_WD_BLOCKS + PRO_WU_BLOCKS + PRO_INIT_BLOCKS)

// ---------------- device scratch ----------------
__device__ int   g_counts[NEXP];
__device__ int   g_tok [NEXP * NTOK];
__device__ float g_gate[NEXP * NTOK];
__device__ float g_xr  [(size_t)NTOK * DDIM];            // tf32-rounded x (router)
__device__ float g_Wdr [(size_t)NEXP * DDIM * HDIM];     // prepped Wd (swizzled tiles)
__device__ float g_Wur [(size_t)NEXP * HDIM * DDIM];     // prepped Wu (swizzled tiles)
__device__ float g_hidden[(size_t)NEXP * NTOK * HDIM];   // tf32-rounded gelu output

// ---------------- helpers ----------------
__device__ __forceinline__ float tf32r(float f) {
    uint32_t u;
    asm("cvt.rna.tf32.f32 %0, %1;" : "=r"(u) : "f"(f));
    return __uint_as_float(u);
}
__device__ __forceinline__ void mma_tf32(float c[4],
                                         uint32_t a0, uint32_t a1, uint32_t a2, uint32_t a3,
                                         uint32_t b0, uint32_t b1) {
    asm volatile(
        "mma.sync.aligned.m16n8k8.row.col.f32.tf32.tf32.f32 "
        "{%0,%1,%2,%3}, {%4,%5,%6,%7}, {%8,%9}, {%0,%1,%2,%3};"
        : "+f"(c[0]), "+f"(c[1]), "+f"(c[2]), "+f"(c[3])
        : "r"(a0), "r"(a1), "r"(a2), "r"(a3), "r"(b0), "r"(b1));
}
__device__ __forceinline__ void cp16(uint32_t dst, const void* src) {
    asm volatile("cp.async.cg.shared.global [%0], [%1], 16;" :: "r"(dst), "l"(src));
}
#define CP_COMMIT() asm volatile("cp.async.commit_group;" ::: "memory")
#define CP_WAIT(n)  asm volatile("cp.async.wait_group %0;" :: "n"(n) : "memory")

// ============================================================
// prologue: one kernel does (a) Wd prep, (b) Wu prep, (c) out zero,
// and zeroes router counters. All three tasks independent.
// Weight prep layout verified bit-exact since Round 6:
//   chunk c' at row k (t = k&3): hb=(c'>>3)^t -> wn=hb>>1, v=hb&1;
//   g=(c'&7)^((t<<1)&7); float nl -> n = nblk*128 + wn*64 + v*32 + nl*8 + g
// ============================================================
__global__ void prologue_kernel(const float* __restrict__ Wd,
                                const float* __restrict__ Wu,
                                float* __restrict__ out) {
    int b = blockIdx.x;
    int tidx = threadIdx.x;
    if (b == 0 && tidx < NEXP) g_counts[tidx] = 0;

    if (b < PRO_WD_BLOCKS) {
        int id = b * 256 + tidx;
        int cp = id & 31;
        int k  = (id >> 5) & 1023;
        int nb = (id >> 15) & 3;
        int e  = id >> 17;
        int t  = k & 3;
        int hb = ((cp >> 3) & 3) ^ t;
        int wn = hb >> 1, v = hb & 1;
        int g  = (cp & 7) ^ ((t << 1) & 7);
        const float* src = Wd + (size_t)e * DDIM * HDIM + (size_t)k * HDIM + nb * 128 + wn * 64 + v * 32 + g;
        float4 o;
        o.x = tf32r(src[0]);
        o.y = tf32r(src[8]);
        o.z = tf32r(src[16]);
        o.w = tf32r(src[24]);
        ((float4*)g_Wdr)[id] = o;
    } else if (b < PRO_WD_BLOCKS + PRO_WU_BLOCKS) {
        int id = (b - PRO_WD_BLOCKS) * 256 + tidx;
        int cp = id & 31;
        int k  = (id >> 5) & 511;
        int nb = (id >> 14) & 7;
        int e  = id >> 17;
        int t  = k & 3;
        int hb = ((cp >> 3) & 3) ^ t;
        int wn = hb >> 1, v = hb & 1;
        int g  = (cp & 7) ^ ((t << 1) & 7);
        const float* src = Wu + (size_t)e * HDIM * DDIM + (size_t)k * DDIM + nb * 128 + wn * 64 + v * 32 + g;
        float4 o;
        o.x = tf32r(src[0]);
        o.y = tf32r(src[8]);
        o.z = tf32r(src[16]);
        o.w = tf32r(src[24]);
        ((float4*)g_Wur)[id] = o;
    } else {
        size_t id = (size_t)(b - PRO_WD_BLOCKS - PRO_WU_BLOCKS) * 256 + tidx;
        ((float4*)out)[id] = make_float4(0.f, 0.f, 0.f, 0.f);
    }
}

// ============================================================
// router — one warp per token; Wr/Wn cached TRANSPOSED in smem
// (conflict-free scalar LDS). FMA values/order identical -> same routing.
// ============================================================
__global__ __launch_bounds__(RT_THREADS) void router_kernel(
    const float* __restrict__ x,
    const float* __restrict__ Wr, const float* __restrict__ br,
    const float* __restrict__ Wn, const float* __restrict__ bn,
    const float* __restrict__ noise) {
    extern __shared__ __align__(16) float sWt[];   // [e][1024] Wr, then [e][1024] Wn
    int tid = threadIdx.x;
#pragma unroll
    for (int i = 0; i < 2; i++) {
        int d = tid + i * RT_THREADS;
        float4 r0 = ((const float4*)(Wr + (size_t)d * NEXP))[0];
        float4 r1 = ((const float4*)(Wr + (size_t)d * NEXP))[1];
        sWt[0 * 1024 + d] = r0.x; sWt[1 * 1024 + d] = r0.y;
        sWt[2 * 1024 + d] = r0.z; sWt[3 * 1024 + d] = r0.w;
        sWt[4 * 1024 + d] = r1.x; sWt[5 * 1024 + d] = r1.y;
        sWt[6 * 1024 + d] = r1.z; sWt[7 * 1024 + d] = r1.w;
        float4 n0 = ((const float4*)(Wn + (size_t)d * NEXP))[0];
        float4 n1 = ((const float4*)(Wn + (size_t)d * NEXP))[1];
        sWt[8192 + 0 * 1024 + d] = n0.x; sWt[8192 + 1 * 1024 + d] = n0.y;
        sWt[8192 + 2 * 1024 + d] = n0.z; sWt[8192 + 3 * 1024 + d] = n0.w;
        sWt[8192 + 4 * 1024 + d] = n1.x; sWt[8192 + 5 * 1024 + d] = n1.y;
        sWt[8192 + 6 * 1024 + d] = n1.z; sWt[8192 + 7 * 1024 + d] = n1.w;
    }
    __syncthreads();

    int gwarp = blockIdx.x * (RT_THREADS / 32) + (tid >> 5);
    int lane  = tid & 31;
    const float* xr = x + (size_t)gwarp * DDIM;
    float* xw = g_xr + (size_t)gwarp * DDIM;

    float accL[NEXP], accN[NEXP];
#pragma unroll
    for (int e = 0; e < NEXP; e++) { accL[e] = 0.f; accN[e] = 0.f; }

    for (int d = lane; d < DDIM; d += 32) {
        float xv = xr[d];
        xw[d] = tf32r(xv);
        accL[0] = fmaf(xv, sWt[0 * 1024 + d], accL[0]);
        accL[1] = fmaf(xv, sWt[1 * 1024 + d], accL[1]);
        accL[2] = fmaf(xv, sWt[2 * 1024 + d], accL[2]);
        accL[3] = fmaf(xv, sWt[3 * 1024 + d], accL[3]);
        accL[4] = fmaf(xv, sWt[4 * 1024 + d], accL[4]);
        accL[5] = fmaf(xv, sWt[5 * 1024 + d], accL[5]);
        accL[6] = fmaf(xv, sWt[6 * 1024 + d], accL[6]);
        accL[7] = fmaf(xv, sWt[7 * 1024 + d], accL[7]);
        accN[0] = fmaf(xv, sWt[8192 + 0 * 1024 + d], accN[0]);
        accN[1] = fmaf(xv, sWt[8192 + 1 * 1024 + d], accN[1]);
        accN[2] = fmaf(xv, sWt[8192 + 2 * 1024 + d], accN[2]);
        accN[3] = fmaf(xv, sWt[8192 + 3 * 1024 + d], accN[3]);
        accN[4] = fmaf(xv, sWt[8192 + 4 * 1024 + d], accN[4]);
        accN[5] = fmaf(xv, sWt[8192 + 5 * 1024 + d], accN[5]);
        accN[6] = fmaf(xv, sWt[8192 + 6 * 1024 + d], accN[6]);
        accN[7] = fmaf(xv, sWt[8192 + 7 * 1024 + d], accN[7]);
    }
#pragma unroll
    for (int off = 16; off > 0; off >>= 1) {
#pragma unroll
        for (int e = 0; e < NEXP; e++) {
            accL[e] += __shfl_down_sync(0xffffffffu, accL[e], off);
            accN[e] += __shfl_down_sync(0xffffffffu, accN[e], off);
        }
    }
    if (lane == 0) {
        float noisy[NEXP];
#pragma unroll
        for (int e = 0; e < NEXP; e++) {
            float nl = accN[e] + bn[e];
            float sp = fmaxf(nl, 0.f) + log1pf(expf(-fabsf(nl)));
            noisy[e] = accL[e] + br[e] + noise[(size_t)gwarp * NEXP + e] * sp;
        }
        int i1 = 0; float v1 = noisy[0];
#pragma unroll
        for (int e = 1; e < NEXP; e++) if (noisy[e] > v1) { v1 = noisy[e]; i1 = e; }
        int i2 = -1; float v2 = -3.4e38f;
#pragma unroll
        for (int e = 0; e < NEXP; e++) if (e != i1 && noisy[e] > v2) { v2 = noisy[e]; i2 = e; }

        float e2 = expf(v2 - v1);
        float s  = 1.0f + e2;
        float g1 = 1.0f / s;
        float g2 = e2 / s;

        int p1 = atomicAdd(&g_counts[i1], 1);
        g_tok [i1 * NTOK + p1] = gwarp;
        g_gate[i1 * NTOK + p1] = g1;
        int p2 = atomicAdd(&g_counts[i2], 1);
        g_tok [i2 * NTOK + p2] = gwarp;
        g_gate[i2 * NTOK + p2] = g2;
    }
}

// ============================================================
// GEMM machinery — R12 exact (best passing): CTA 128x128, 8 warps
// (32x64 tiles), NSTAGE=3 cp.async, single sync/iter (wait BEFORE sync).
// ============================================================
struct Src {
    const float* arow[4];   // gathered A row ptrs (+chunk offset applied)
    const float* bbase;     // prepped weight tile base (swizzled rows of 128 floats)
};

__device__ __forceinline__ void compute_stage(const char* smem, int st,
                                              int warp_m, int wnbit, int g, int t,
                                              float acc[2][8][4]) {
    const uint32_t* As = (const uint32_t*)(smem + st * STAGE_BYTES);
    const uint4*    Bs = (const uint4*)(smem + st * STAGE_BYTES + A_BYTES);
    const int glo = g ^ ((t << 1) & 7);
#pragma unroll
    for (int ks = 0; ks < 4; ks++) {
        int kk = ks * 8;
        uint32_t af[2][4];
#pragma unroll
        for (int mi = 0; mi < 2; mi++) {
            int mr = warp_m + mi * 16 + g;
            af[mi][0] = As[(mr    ) * ASTRIDE + kk + t];
            af[mi][1] = As[(mr + 8) * ASTRIDE + kk + t];
            af[mi][2] = As[(mr    ) * ASTRIDE + kk + t + 4];
            af[mi][3] = As[(mr + 8) * ASTRIDE + kk + t + 4];
        }
        uint4 b0[2], b1[2];
#pragma unroll
        for (int v = 0; v < 2; v++) {
            int cidx = ((((wnbit << 1) | v) ^ t) << 3) | glo;
            b0[v] = Bs[(kk + t    ) * 32 + cidx];
            b1[v] = Bs[(kk + t + 4) * 32 + cidx];
        }
#pragma unroll
        for (int mi = 0; mi < 2; mi++) {
            mma_tf32(acc[mi][0], af[mi][0], af[mi][1], af[mi][2], af[mi][3], b0[0].x, b1[0].x);
            mma_tf32(acc[mi][1], af[mi][0], af[mi][1], af[mi][2], af[mi][3], b0[0].y, b1[0].y);
            mma_tf32(acc[mi][2], af[mi][0], af[mi][1], af[mi][2], af[mi][3], b0[0].z, b1[0].z);
            mma_tf32(acc[mi][3], af[mi][0], af[mi][1], af[mi][2], af[mi][3], b0[0].w, b1[0].w);
            mma_tf32(acc[mi][4], af[mi][0], af[mi][1], af[mi][2], af[mi][3], b0[1].x, b1[1].x);
            mma_tf32(acc[mi][5], af[mi][0], af[mi][1], af[mi][2], af[mi][3], b0[1].y, b1[1].y);
            mma_tf32(acc[mi][6], af[mi][0], af[mi][1], af[mi][2], af[mi][3], b0[1].z, b1[1].z);
            mma_tf32(acc[mi][7], af[mi][0], af[mi][1], af[mi][2], af[mi][3], b0[1].w, b1[1].w);
        }
    }
}

#define LOAD_ST(s)                                                               \
    do {                                                                         \
        _Pragma("unroll") for (int j = 0; j < 4; j++)                            \
            cp16(stA[s] + aoff[j], gA[j]);                                       \
        _Pragma("unroll") for (int j = 0; j < 4; j++)                            \
            cp16(stB[s] + boff[j], gB + (boff[j] >> 2));                         \
        CP_COMMIT();                                                             \
        _Pragma("unroll") for (int j = 0; j < 4; j++) gA[j] += BK;               \
        gB += BK * BN;                                                           \
    } while (0)

#define GEMM_MAINLOOP(NITER)                                                     \
    uint32_t stA[NSTAGE], stB[NSTAGE];                                           \
    uint32_t aoff[4], boff[4];                                                   \
    const float* gA[4];                                                          \
    const float* gB;                                                             \
    {                                                                            \
        uint32_t sbase = (uint32_t)__cvta_generic_to_shared(smem);               \
        _Pragma("unroll") for (int s = 0; s < NSTAGE; s++) {                     \
            stA[s] = sbase + s * STAGE_BYTES;                                    \
            stB[s] = stA[s] + A_BYTES;                                           \
        }                                                                        \
        int c16 = tid & 7;                                                       \
        _Pragma("unroll") for (int j = 0; j < 4; j++) {                          \
            aoff[j] = ((tid >> 3) + 32 * j) * (ASTRIDE * 4) + c16 * 16;          \
            boff[j] = (uint32_t)(j * 256 + tid) * 16;                            \
            gA[j] = src.arow[j];                                                 \
        }                                                                        \
        gB = src.bbase;                                                          \
    }                                                                            \
    LOAD_ST(0);                                                                  \
    {                                                                            \
        int st = 0;                                                              \
        for (int i = 0; i < (NITER); i++) {                                      \
            if (i + 1 < (NITER)) {                                               \
                int st1 = st + 1; if (st1 == NSTAGE) st1 = 0;                    \
                LOAD_ST(st1);                                                    \
                CP_WAIT(1);                                                      \
            } else { CP_WAIT(0); }                                               \
            __syncthreads();                                                     \
            compute_stage(smem, st, warp_m, wnbit, g, t, acc);                   \
            if (++st == NSTAGE) st = 0;                                          \
        }                                                                        \
    }

// ============================================================
// grouped GEMM #1 — hidden = tf32r(gelu(x[toks] @ Wd + bd))
// ============================================================
__global__ __launch_bounds__(256, 2) void expert_down_mma(const float* __restrict__ bd)
{
    extern __shared__ __align__(16) char smem[];
    int e  = blockIdx.z;
    int ne = g_counts[e];
    int m0 = blockIdx.y * BM;
    if (m0 >= ne) return;
    int n0 = blockIdx.x * BN;

    int tid  = threadIdx.x;
    int lane = tid & 31;
    int wid  = tid >> 5;
    int warp_m = (wid & 3) * 32;
    int wnbit  = wid >> 2;          // 0 or 1
    int warp_n = wnbit * 64;
    int g = lane >> 2, t = lane & 3;

    Src src;
    int c16 = tid & 7;
#pragma unroll
    for (int j = 0; j < 4; j++) {
        int m = m0 + (tid >> 3) + 32 * j;
        int tok = (m < ne) ? g_tok[e * NTOK + m] : g_tok[e * NTOK + m0];
        src.arow[j] = g_xr + (size_t)tok * DDIM + c16 * 4;
    }
    src.bbase = g_Wdr + ((size_t)(e * 4 + blockIdx.x) * DDIM) * BN;

    float acc[2][8][4];
#pragma unroll
    for (int mi = 0; mi < 2; mi++)
#pragma unroll
        for (int ni = 0; ni < 8; ni++)
#pragma unroll
            for (int j = 0; j < 4; j++) acc[mi][ni][j] = 0.f;

    GEMM_MAINLOOP(DDIM / BK)

    // epilogue: bias + exact GELU + tf32 round
#pragma unroll
    for (int mi = 0; mi < 2; mi++) {
        int m1 = m0 + warp_m + mi * 16 + g;
        int m2 = m1 + 8;
#pragma unroll
        for (int ni = 0; ni < 8; ni++) {
            int n = n0 + warp_n + ni * 8 + 2 * t;
            float b0v = bd[e * HDIM + n];
            float b1v = bd[e * HDIM + n + 1];
            if (m1 < ne) {
                float h0 = acc[mi][ni][0] + b0v;
                float h1 = acc[mi][ni][1] + b1v;
                h0 = tf32r(0.5f * h0 * (1.0f + erff(h0 * 0.70710678118654752f)));
                h1 = tf32r(0.5f * h1 * (1.0f + erff(h1 * 0.70710678118654752f)));
                *(float2*)(g_hidden + ((size_t)e * NTOK + m1) * HDIM + n) = make_float2(h0, h1);
            }
            if (m2 < ne) {
                float h2 = acc[mi][ni][2] + b0v;
                float h3 = acc[mi][ni][3] + b1v;
                h2 = tf32r(0.5f * h2 * (1.0f + erff(h2 * 0.70710678118654752f)));
                h3 = tf32r(0.5f * h3 * (1.0f + erff(h3 * 0.70710678118654752f)));
                *(float2*)(g_hidden + ((size_t)e * NTOK + m2) * HDIM + n) = make_float2(h2, h3);
            }
        }
    }
}

// ============================================================
// grouped GEMM #2 — out[tok] += gate * (hidden @ Wu + bu)
// ============================================================
__global__ __launch_bounds__(256, 2) void expert_up_mma(
    const float* __restrict__ bu, float* __restrict__ out)
{
    extern __shared__ __align__(16) char smem[];
    int e  = blockIdx.z;
    int ne = g_counts[e];
    int m0 = blockIdx.y * BM;
    if (m0 >= ne) return;
    int n0 = blockIdx.x * BN;

    int tid  = threadIdx.x;
    int lane = tid & 31;
    int wid  = tid >> 5;
    int warp_m = (wid & 3) * 32;
    int wnbit  = wid >> 2;
    int warp_n = wnbit * 64;
    int g = lane >> 2, t = lane & 3;

    Src src;
    int c16 = tid & 7;
#pragma unroll
    for (int j = 0; j < 4; j++) {
        int m = m0 + (tid >> 3) + 32 * j;
        int mm = (m < ne) ? m : m0;   // clamp: garbage rows never reach valid accumulators
        src.arow[j] = g_hidden + ((size_t)e * NTOK + mm) * HDIM + c16 * 4;
    }
    src.bbase = g_Wur + ((size_t)(e * 8 + blockIdx.x) * HDIM) * BN;

    float acc[2][8][4];
#pragma unroll
    for (int mi = 0; mi < 2; mi++)
#pragma unroll
        for (int ni = 0; ni < 8; ni++)
#pragma unroll
            for (int j = 0; j < 4; j++) acc[mi][ni][j] = 0.f;

    GEMM_MAINLOOP(HDIM / BK)

    // epilogue: bias + gate * atomicAdd (2 commutative adds/element -> deterministic)
#pragma unroll
    for (int mi = 0; mi < 2; mi++) {
        int m1 = m0 + warp_m + mi * 16 + g;
        int m2 = m1 + 8;
        int   tok1 = 0, tok2 = 0;
        float gt1 = 0.f, gt2 = 0.f;
        if (m1 < ne) { tok1 = g_tok[e * NTOK + m1]; gt1 = g_gate[e * NTOK + m1]; }
        if (m2 < ne) { tok2 = g_tok[e * NTOK + m2]; gt2 = g_gate[e * NTOK + m2]; }
#pragma unroll
        for (int ni = 0; ni < 8; ni++) {
            int n = n0 + warp_n + ni * 8 + 2 * t;
            float b0v = bu[e * DDIM + n];
            float b1v = bu[e * DDIM + n + 1];
            if (m1 < ne) {
                atomicAdd(out + (size_t)tok1 * DDIM + n,     (acc[mi][ni][0] + b0v) * gt1);
                atomicAdd(out + (size_t)tok1 * DDIM + n + 1, (acc[mi][ni][1] + b1v) * gt1);
            }
            if (m2 < ne) {
                atomicAdd(out + (size_t)tok2 * DDIM + n,     (acc[mi][ni][2] + b0v) * gt2);
                atomicAdd(out + (size_t)tok2 * DDIM + n + 1, (acc[mi][ni][3] + b1v) * gt2);
            }
        }
    }
}

// ============================================================
// Host launcher — prologue(0) -> router(1) -> down(2) -> up(3, ncu).
// Dependencies: prologue zeroes counters + out before router/up.
// ============================================================
extern "C" void kernel_launch(void* const* d_in, const int* in_sizes, int n_in,
                              void* d_out, int out_size) {
    const float* x     = (const float*)d_in[0];
    const float* Wr    = (const float*)d_in[1];
    const float* br    = (const float*)d_in[2];
    const float* Wn    = (const float*)d_in[3];
    const float* bn    = (const float*)d_in[4];
    const float* Wd    = (const float*)d_in[5];
    const float* bd    = (const float*)d_in[6];
    const float* Wu    = (const float*)d_in[7];
    const float* bu    = (const float*)d_in[8];
    const float* noise = (const float*)d_in[9];
    float* out = (float*)d_out;

    cudaFuncSetAttribute(expert_down_mma, cudaFuncAttributeMaxDynamicSharedMemorySize, SMEM_BYTES);
    cudaFuncSetAttribute(expert_up_mma,   cudaFuncAttributeMaxDynamicSharedMemorySize, SMEM_BYTES);
    cudaFuncSetAttribute(router_kernel,   cudaFuncAttributeMaxDynamicSharedMemorySize, RT_SMEM);

    prologue_kernel<<<PRO_BLOCKS, 256>>>(Wd, Wu, out);                                  // idx 0
    router_kernel<<<NTOK / (RT_THREADS / 32), RT_THREADS, RT_SMEM>>>(x, Wr, br, Wn, bn, noise); // idx 1
    expert_down_mma<<<dim3(HDIM / BN, NTOK / BM, NEXP), 256, SMEM_BYTES>>>(bd);         // idx 2
    expert_up_mma<<<dim3(DDIM / BN, NTOK / BM, NEXP), 256, SMEM_BYTES>>>(bu, out);      // idx 3 (ncu)
}